// round 11
// baseline (speedup 1.0000x reference)
#include <cuda_runtime.h>
#include <cuda_bf16.h>

// PatchFFTLoss round 11: 4 lanes per patch = (tensor) x (row-half).
//  - lane (t,h): tensor t, rows 4h..4h+3. Real row FFTs keep v=0..4.
//  - column FFT: stage 1 (dist 4) via xor-2 shuffles, then 4-pt DFT
//    in-register. Lane h=0 owns even u-bins {0,4,2,6}, h=1 odd {1,5,3,7}.
//  - epilogue: g = sign*log2(1+|x|/8) (ortho scale folded in), pair-diff
//    across tensor lanes via xor-1 shuffles; canonical weights per lane.
//  - 32 floats of live state -> 64-reg budget -> 8 CTAs/SM (occ 50%).
//  - static grid, fused last-block-done reduction, bit-deterministic.

#define NPATCH   (16 * 3 * 64 * 64)       // 196608
#define NTHREADS (NPATCH * 4)             // 786432
#define BLOCK    128
#define NBLOCKS  (NTHREADS / BLOCK)       // 6144
#define LN2      0.69314718055994530942f
#define FINAL_SCALE ((LN2 * LN2) / (2.0f * 12582912.0f))
#define FULLM    0xffffffffu

__device__ float g_partials[NBLOCKS];
__device__ unsigned int g_count = 0;

// g on unnormalized FFT value: sign(x) * log2(1 + |x|/8)
__device__ __forceinline__ float gfun(float x) {
    return copysignf(__log2f(fmaf(0.125f, fabsf(x), 1.0f)), x);
}

// d^2 of g across the (input,target) lane pair (xor 1)
__device__ __forceinline__ float ddq(float x) {
    float gv = gfun(x);
    float d = gv - __shfl_xor_sync(FULLM, gv, 1);
    return d * d;
}

__global__ void __launch_bounds__(BLOCK, 8)
patch_fft_loss_kernel(const float* __restrict__ inp,
                      const float* __restrict__ tgt,
                      float* __restrict__ out)
{
    const int gid = blockIdx.x * BLOCK + threadIdx.x;
    const int t  = gid & 1;           // tensor lane bit
    const int h  = (gid >> 1) & 1;    // row-half lane bit
    const int p  = gid >> 2;          // patch index
    const int pw = p & 63;
    const int ph = (p >> 6) & 63;
    const int bc = p >> 12;
    const float* __restrict__ src = t ? tgt : inp;
    const size_t base = ((size_t)(bc * 512 + ph * 8 + 4 * h)) * 512
                      + (size_t)pw * 8;

    const float C = 0.70710678118654752440f;
    // stage-1 combine sign and per-lane twiddles W8^{h*j}
    const float sgn = h ? -1.0f : 1.0f;
    const float w1r = h ?  C   : 1.0f, w1i = h ? -C   : 0.0f;
    const float w2r = h ?  0.0f: 1.0f, w2i = h ? -1.0f: 0.0f;
    const float w3r = h ? -C   : 1.0f, w3i = h ? -C   : 0.0f;
    // real-column weights: slotA = u0/u1 -> (1,2); slotB = u4/u5 -> (1,0)
    const float wa = h ? 2.0f : 1.0f;
    const float wb = h ? 0.0f : 1.0f;

    // ---- front-batched loads: 8 LDG.128 (rows 4h .. 4h+3) ----
    float4 la[4], lb[4];
    #pragma unroll
    for (int j = 0; j < 4; j++) {
        const float* rp = src + base + (size_t)j * 512;
        la[j] = *(const float4*)(rp);
        lb[j] = *(const float4*)(rp + 4);
    }

    // ---- 4 real row FFTs (unnormalized), keep v = 0..4 ----
    float R0[4], R4[4];
    float X1r[4], X1i[4], X2r[4], X2i[4], X3r[4], X3i[4];
    #pragma unroll
    for (int j = 0; j < 4; j++) {
        float x0=la[j].x, x1=la[j].y, x2=la[j].z, x3=la[j].w;
        float x4=lb[j].x, x5=lb[j].y, x6=lb[j].z, x7=lb[j].w;
        float a04p=x0+x4, a04m=x0-x4;
        float a26p=x2+x6, a26m=x2-x6;
        float E0=a04p+a26p, E2=a04p-a26p;
        float b15p=x1+x5, b15m=x1-x5;
        float b37p=x3+x7, b37m=x3-x7;
        float O0=b15p+b37p, O2=b15p-b37p;
        float t1 =  C*(b15m-b37m);
        float t2 = -C*(b15m+b37m);
        R0[j]  = E0 + O0;
        R4[j]  = E0 - O0;
        X1r[j] = a04m + t1;  X1i[j] = -a26m + t2;
        X2r[j] = E2;         X2i[j] = -O2;
        X3r[j] = a04m - t1;  X3i[j] =  a26m + t2;
    }

    float accW = 0.0f;   // explicitly-weighted terms (real columns, slots A/B)
    float acc2 = 0.0f;   // weight-2 terms

    // ---- real columns v = 0, 4 ----
    // stage 1: s[j] = peer + sgn*own (xor 2); lane h=1 applies W8^j.
    // 4-pt DFT bins: Ua=u(0/1), Ub=u(4/5), Uc=u(2/3); Ud has weight 0 -> skip.
    #pragma unroll
    for (int k = 0; k < 2; k++) {
        const float* c = k ? R4 : R0;
        float s0 = fmaf(sgn, c[0], __shfl_xor_sync(FULLM, c[0], 2));
        float s1 = fmaf(sgn, c[1], __shfl_xor_sync(FULLM, c[1], 2));
        float s2 = fmaf(sgn, c[2], __shfl_xor_sync(FULLM, c[2], 2));
        float s3 = fmaf(sgn, c[3], __shfl_xor_sync(FULLM, c[3], 2));
        float Q1r = s1*w1r, Q1i = s1*w1i;
        float Q2r = s2*w2r, Q2i = s2*w2i;
        float Q3r = s3*w3r, Q3i = s3*w3i;
        float s0r = s0 + Q2r, s0i = Q2i;
        float s1r = Q1r + Q3r, s1i = Q1i + Q3i;
        float d0r = s0 - Q2r, d0i = -Q2i;
        float er  = Q1r - Q3r, ei = Q1i - Q3i;
        float Uar = s0r + s1r, Uai = s0i + s1i;
        float Ubr = s0r - s1r, Ubi = s0i - s1i;
        float Ucr = d0r + ei,  Uci = d0i - er;
        accW = fmaf(wa, ddq(Uar) + ddq(Uai), accW);
        accW = fmaf(wb, ddq(Ubr) + ddq(Ubi), accW);
        acc2 += ddq(Ucr) + ddq(Uci);
    }

    // ---- complex columns v = 1, 2, 3: all bins weight 2 ----
    #pragma unroll
    for (int k = 0; k < 3; k++) {
        const float* zr = (k == 0) ? X1r : (k == 1) ? X2r : X3r;
        const float* zi = (k == 0) ? X1i : (k == 1) ? X2i : X3i;
        float sr0 = fmaf(sgn, zr[0], __shfl_xor_sync(FULLM, zr[0], 2));
        float si0 = fmaf(sgn, zi[0], __shfl_xor_sync(FULLM, zi[0], 2));
        float sr1 = fmaf(sgn, zr[1], __shfl_xor_sync(FULLM, zr[1], 2));
        float si1 = fmaf(sgn, zi[1], __shfl_xor_sync(FULLM, zi[1], 2));
        float sr2 = fmaf(sgn, zr[2], __shfl_xor_sync(FULLM, zr[2], 2));
        float si2 = fmaf(sgn, zi[2], __shfl_xor_sync(FULLM, zi[2], 2));
        float sr3 = fmaf(sgn, zr[3], __shfl_xor_sync(FULLM, zr[3], 2));
        float si3 = fmaf(sgn, zi[3], __shfl_xor_sync(FULLM, zi[3], 2));
        float Q1r = sr1*w1r - si1*w1i, Q1i = sr1*w1i + si1*w1r;
        float Q2r = sr2*w2r - si2*w2i, Q2i = sr2*w2i + si2*w2r;
        float Q3r = sr3*w3r - si3*w3i, Q3i = sr3*w3i + si3*w3r;
        float s0r = sr0 + Q2r, s0i = si0 + Q2i;
        float s1r = Q1r + Q3r, s1i = Q1i + Q3i;
        float d0r = sr0 - Q2r, d0i = si0 - Q2i;
        float er  = Q1r - Q3r, ei  = Q1i - Q3i;
        float Uar = s0r + s1r, Uai = s0i + s1i;
        float Ubr = s0r - s1r, Ubi = s0i - s1i;
        float Ucr = d0r + ei,  Uci = d0i - er;
        float Udr = d0r - ei,  Udi = d0i + er;
        acc2 += ddq(Uar) + ddq(Uai);
        acc2 += ddq(Ubr) + ddq(Ubi);
        acc2 += ddq(Ucr) + ddq(Uci);
        acc2 += ddq(Udr) + ddq(Udi);
    }

    float acc = fmaf(2.0f, acc2, accW);

    // ---- deterministic reduction: warp -> block -> last-block-done global ----
    #pragma unroll
    for (int o = 16; o > 0; o >>= 1)
        acc += __shfl_xor_sync(FULLM, acc, o);

    __shared__ float smw[BLOCK / 32];
    __shared__ bool isLast;
    if ((threadIdx.x & 31) == 0) smw[threadIdx.x >> 5] = acc;
    __syncthreads();
    if (threadIdx.x == 0) {
        float s = 0.0f;
        #pragma unroll
        for (int i = 0; i < BLOCK / 32; i++) s += smw[i];
        g_partials[blockIdx.x] = s;
        __threadfence();
        unsigned old = atomicInc(&g_count, NBLOCKS - 1);  // wraps to 0 on last
        isLast = (old == NBLOCKS - 1);
    }
    __syncthreads();

    if (isLast) {
        float a = 0.0f;
        #pragma unroll
        for (int i = 0; i < NBLOCKS / BLOCK; i++)
            a += __ldcg(&g_partials[threadIdx.x + i * BLOCK]);
        #pragma unroll
        for (int o = 16; o > 0; o >>= 1)
            a += __shfl_xor_sync(FULLM, a, o);
        if ((threadIdx.x & 31) == 0) smw[threadIdx.x >> 5] = a;
        __syncthreads();
        if (threadIdx.x == 0) {
            float s = 0.0f;
            #pragma unroll
            for (int i = 0; i < BLOCK / 32; i++) s += smw[i];
            out[0] = s * FINAL_SCALE;
        }
    }
}

extern "C" void kernel_launch(void* const* d_in, const int* in_sizes, int n_in,
                              void* d_out, int out_size)
{
    const float* inp = (const float*)d_in[0];
    const float* tgt = (const float*)d_in[1];
    patch_fft_loss_kernel<<<NBLOCKS, BLOCK>>>(inp, tgt, (float*)d_out);
}

// round 12
// speedup vs baseline: 1.1415x; 1.1415x over previous
#include <cuda_runtime.h>
#include <cuda_bf16.h>

// PatchFFTLoss round 12: R8 scalar math + R9 scale-fold + cross-patch
// software pipelining.
//  - thread pair (t=0 input, t=1 target) processes TWO adjacent patches
//    (p = 2q, 2q+1): all 32 LDG.128 issued up front, so patch-1's DRAM
//    latency is hidden under patch-0's compute (intra-warp overlap).
//  - per thread+patch: real-input 8x8 FFT (Hermitian in v), canonical bins
//    only; g = sign*log2(1+|x|/8) (ortho 1/8 folded into the log argument);
//    pair-diff across tensor lanes via ONE xor-1 shuffle per g.
//  - no f32x2 packing (R9 showed pack MOVs raise total issue count).
//  - static grid, fused last-block-done reduction, bit-deterministic.

#define NPATCH   (16 * 3 * 64 * 64)       // 196608
#define NTHREADS NPATCH                   // 2 lanes/patch x 2 patches/thread
#define BLOCK    128
#define NBLOCKS  (NTHREADS / BLOCK)       // 1536
#define LN2      0.69314718055994530942f
#define FINAL_SCALE ((LN2 * LN2) / (2.0f * 12582912.0f))
#define FULLM    0xffffffffu

__device__ float g_partials[NBLOCKS];
__device__ unsigned int g_count = 0;

// g on unnormalized FFT value: sign(x) * log2(1 + |x|/8)
__device__ __forceinline__ float gfun(float x) {
    return copysignf(__log2f(fmaf(0.125f, fabsf(x), 1.0f)), x);
}

// d^2 of g across the (input,target) lane pair (xor 1)
__device__ __forceinline__ float ddq(float x) {
    float gv = gfun(x);
    float d = gv - __shfl_xor_sync(FULLM, gv, 1);
    return d * d;
}

// scalar complex 8-pt FFT in place, natural-order bins (validated r2-r11)
__device__ __forceinline__ void fft8c(float* xr, float* xi)
{
    const float C = 0.70710678118654752440f;
    float A0r=xr[0]+xr[4], A0i=xi[0]+xi[4];
    float A1r=xr[1]+xr[5], A1i=xi[1]+xi[5];
    float A2r=xr[2]+xr[6], A2i=xi[2]+xi[6];
    float A3r=xr[3]+xr[7], A3i=xi[3]+xi[7];
    float B0r=xr[0]-xr[4], B0i=xi[0]-xi[4];
    float d1r=xr[1]-xr[5], d1i=xi[1]-xi[5];
    float B1r=C*(d1r+d1i), B1i=C*(d1i-d1r);
    float B2r=xi[2]-xi[6], B2i=xr[6]-xr[2];
    float d3r=xr[3]-xr[7], d3i=xi[3]-xi[7];
    float B3r=C*(d3i-d3r), B3i=-C*(d3r+d3i);

    float A20r=A0r+A2r, A20i=A0i+A2i;
    float A22r=A0r-A2r, A22i=A0i-A2i;
    float A21r=A1r+A3r, A21i=A1i+A3i;
    float A23r=A1i-A3i, A23i=A3r-A1r;
    float B20r=B0r+B2r, B20i=B0i+B2i;
    float B22r=B0r-B2r, B22i=B0i-B2i;
    float B21r=B1r+B3r, B21i=B1i+B3i;
    float B23r=B1i-B3i, B23i=B3r-B1r;

    xr[0]=A20r+A21r; xi[0]=A20i+A21i;
    xr[4]=A20r-A21r; xi[4]=A20i-A21i;
    xr[2]=A22r+A23r; xi[2]=A22i+A23i;
    xr[6]=A22r-A23r; xi[6]=A22i-A23i;
    xr[1]=B20r+B21r; xi[1]=B20i+B21i;
    xr[5]=B20r-B21r; xi[5]=B20i-B21i;
    xr[3]=B22r+B23r; xi[3]=B22i+B23i;
    xr[7]=B22r-B23r; xi[7]=B22i-B23i;
}

// full per-patch loss from raw rows (la = cols 0-3, lb = cols 4-7)
__device__ __forceinline__ void patch_loss(const float4* la, const float4* lb,
                                           float& acc1, float& acc2)
{
    const float C = 0.70710678118654752440f;

    // real row FFTs (unnormalized), keep v = 0..4
    float R0[8], R4[8];
    float X1r[8], X1i[8], X2r[8], X2i[8], X3r[8], X3i[8];
    #pragma unroll
    for (int r = 0; r < 8; r++) {
        float x0=la[r].x, x1=la[r].y, x2=la[r].z, x3=la[r].w;
        float x4=lb[r].x, x5=lb[r].y, x6=lb[r].z, x7=lb[r].w;
        float a04p=x0+x4, a04m=x0-x4;
        float a26p=x2+x6, a26m=x2-x6;
        float E0=a04p+a26p, E2=a04p-a26p;
        float b15p=x1+x5, b15m=x1-x5;
        float b37p=x3+x7, b37m=x3-x7;
        float O0=b15p+b37p, O2=b15p-b37p;
        float t1 =  C*(b15m-b37m);
        float t2 = -C*(b15m+b37m);
        R0[r]  = E0 + O0;
        R4[r]  = E0 - O0;
        X1r[r] = a04m + t1;  X1i[r] = -a26m + t2;
        X2r[r] = E2;         X2i[r] = -O2;
        X3r[r] = a04m - t1;  X3i[r] =  a26m + t2;
    }

    // columns v = 0 and v = 4: real FFT, bins u = 0..4
    #pragma unroll
    for (int k = 0; k < 2; k++) {
        const float* c = k ? R4 : R0;
        float a04p=c[0]+c[4], a04m=c[0]-c[4];
        float a26p=c[2]+c[6], a26m=c[2]-c[6];
        float E0=a04p+a26p, E2=a04p-a26p;
        float b15p=c[1]+c[5], b15m=c[1]-c[5];
        float b37p=c[3]+c[7], b37m=c[3]-c[7];
        float O0=b15p+b37p, O2=b15p-b37p;
        float t1 =  C*(b15m-b37m);
        float t2 = -C*(b15m+b37m);
        // u=0,4 self-conjugate (imag exactly 0): weight 1
        acc1 += ddq(E0 + O0);
        acc1 += ddq(E0 - O0);
        // u=1..3: weight 2
        acc2 += ddq(a04m + t1) + ddq(-a26m + t2);
        acc2 += ddq(E2)        + ddq(-O2);
        acc2 += ddq(a04m - t1) + ddq( a26m + t2);
    }

    // columns v = 1..3: complex FFT, all u, weight 2
    fft8c(X1r, X1i);
    #pragma unroll
    for (int u = 0; u < 8; u++) acc2 += ddq(X1r[u]) + ddq(X1i[u]);
    fft8c(X2r, X2i);
    #pragma unroll
    for (int u = 0; u < 8; u++) acc2 += ddq(X2r[u]) + ddq(X2i[u]);
    fft8c(X3r, X3i);
    #pragma unroll
    for (int u = 0; u < 8; u++) acc2 += ddq(X3r[u]) + ddq(X3i[u]);
}

__global__ void __launch_bounds__(BLOCK, 3)
patch_fft_loss_kernel(const float* __restrict__ inp,
                      const float* __restrict__ tgt,
                      float* __restrict__ out)
{
    const int gid = blockIdx.x * BLOCK + threadIdx.x;
    const int t  = gid & 1;           // 0 = input, 1 = target
    const int q  = gid >> 1;          // patch-pair index; patches 2q, 2q+1
    const int p0 = 2 * q;
    const int pw = p0 & 63;           // even
    const int ph = (p0 >> 6) & 63;
    const int bc = p0 >> 12;
    const float* __restrict__ src = t ? tgt : inp;
    const size_t base = ((size_t)(bc * 512 + ph * 8)) * 512 + (size_t)pw * 8;
    // patch 2q+1 is the adjacent 8x8 tile: +8 floats in the same rows

    // ---- issue ALL 32 LDG.128 (both patches) before any arithmetic ----
    float4 la0[8], lb0[8], la1[8], lb1[8];
    #pragma unroll
    for (int r = 0; r < 8; r++) {
        const float* rp = src + base + (size_t)r * 512;
        la0[r] = *(const float4*)(rp);
        lb0[r] = *(const float4*)(rp + 4);
        la1[r] = *(const float4*)(rp + 8);
        lb1[r] = *(const float4*)(rp + 12);
    }

    // ---- compute patch 0 (patch 1's loads still in flight) ----
    float acc1 = 0.0f, acc2 = 0.0f;
    patch_loss(la0, lb0, acc1, acc2);
    // ---- compute patch 1 ----
    patch_loss(la1, lb1, acc1, acc2);

    float acc = fmaf(2.0f, acc2, acc1);

    // ---- deterministic reduction: warp -> block -> last-block-done global ----
    #pragma unroll
    for (int o = 16; o > 0; o >>= 1)
        acc += __shfl_xor_sync(FULLM, acc, o);

    __shared__ float smw[BLOCK / 32];
    __shared__ bool isLast;
    if ((threadIdx.x & 31) == 0) smw[threadIdx.x >> 5] = acc;
    __syncthreads();
    if (threadIdx.x == 0) {
        float s = 0.0f;
        #pragma unroll
        for (int i = 0; i < BLOCK / 32; i++) s += smw[i];
        g_partials[blockIdx.x] = s;
        __threadfence();
        unsigned old = atomicInc(&g_count, NBLOCKS - 1);  // wraps to 0 on last
        isLast = (old == NBLOCKS - 1);
    }
    __syncthreads();

    if (isLast) {
        float a = 0.0f;
        #pragma unroll
        for (int i = 0; i < NBLOCKS / BLOCK; i++)
            a += __ldcg(&g_partials[threadIdx.x + i * BLOCK]);
        #pragma unroll
        for (int o = 16; o > 0; o >>= 1)
            a += __shfl_xor_sync(FULLM, a, o);
        if ((threadIdx.x & 31) == 0) smw[threadIdx.x >> 5] = a;
        __syncthreads();
        if (threadIdx.x == 0) {
            float s = 0.0f;
            #pragma unroll
            for (int i = 0; i < BLOCK / 32; i++) s += smw[i];
            out[0] = s * FINAL_SCALE;
        }
    }
}

extern "C" void kernel_launch(void* const* d_in, const int* in_sizes, int n_in,
                              void* d_out, int out_size)
{
    const float* inp = (const float*)d_in[0];
    const float* tgt = (const float*)d_in[1];
    patch_fft_loss_kernel<<<NBLOCKS, BLOCK>>>(inp, tgt, (float*)d_out);
}